// round 1
// baseline (speedup 1.0000x reference)
#include <cuda_runtime.h>
#include <math.h>

#define NQ    12
#define DIM   4096
#define KS    6
#define BATCH 256
#define SEQ   128
#define DEMB  512
#define NCLS  8

// scratch for encoder -> quantum handoff (no allocation allowed)
__device__ float g_x[BATCH * NQ];

__device__ __forceinline__ int physaddr(int i) { return i ^ ((i >> 4) & 0xF); }

// Composition of the CNOT ring: out bits 0..10 = suffix parity of input bits,
// out bit 11 = parity(bits 0..10). Pure GF(2)-linear map.
__device__ __forceinline__ int permT(int x) {
    int p = x ^ (x >> 1);
    p ^= p >> 2;
    p ^= p >> 4;
    p ^= p >> 8;
    return (p & 0x7FF) | (((p ^ (x >> 11)) & 1) << 11);
}

// ---------------------------------------------------------------------------
// Encoder: embed -> masked mean pool -> tanh(linear)*pi, fused.
// One CTA per sample, 128 threads, each thread owns 4 of the 512 dims.
// ---------------------------------------------------------------------------
__global__ void __launch_bounds__(SEQ) encoder_kernel(
    const int* __restrict__ ids, const int* __restrict__ mask,
    const float* __restrict__ emb, const float* __restrict__ pw,
    const float* __restrict__ pb)
{
    int b = blockIdx.x, t = threadIdx.x;
    __shared__ int   sid[SEQ];
    __shared__ float smk[SEQ];
    __shared__ float red[4][NQ];
    sid[t] = ids[b * SEQ + t];
    smk[t] = (float)mask[b * SEQ + t];
    __syncthreads();

    float a0 = 0.f, a1 = 0.f, a2 = 0.f, a3 = 0.f, cnt = 0.f;
    for (int s = 0; s < SEQ; s++) {
        float m = smk[s];
        cnt += m;
        if (m != 0.f) {
            const float4 e = __ldg((const float4*)(emb + (size_t)sid[s] * DEMB + t * 4));
            a0 += m * e.x; a1 += m * e.y; a2 += m * e.z; a3 += m * e.w;
        }
    }
    float inv = 1.0f / fmaxf(cnt, 1.0f);

    float z[NQ];
#pragma unroll
    for (int q = 0; q < NQ; q++) {
        const float4 w = __ldg((const float4*)(pw + q * DEMB + t * 4));
        z[q] = a0 * w.x + a1 * w.y + a2 * w.z + a3 * w.w;
    }
#pragma unroll
    for (int q = 0; q < NQ; q++) {
#pragma unroll
        for (int off = 16; off; off >>= 1)
            z[q] += __shfl_down_sync(0xffffffffu, z[q], off);
    }
    int w = t >> 5, l = t & 31;
    if (l == 0) {
#pragma unroll
        for (int q = 0; q < NQ; q++) red[w][q] = z[q];
    }
    __syncthreads();
    if (t < NQ) {
        float s = red[0][t] + red[1][t] + red[2][t] + red[3][t];
        g_x[b * NQ + t] = tanhf(s * inv + pb[t]) * 3.14159265358979f;
    }
}

// Apply 4 fused single-qubit gates (one per butterfly level) to a 16-amp
// register group. Level k2 -> local bit k2 -> wire (wtop - k2).
__device__ __forceinline__ void apply4(float2 v[16], const float2 (*gm)[4], int wtop) {
#pragma unroll
    for (int k2 = 0; k2 < 4; k2++) {
        float2 m00 = gm[wtop - k2][0];
        float2 m01 = gm[wtop - k2][1];
        float2 m10 = gm[wtop - k2][2];
        float2 m11 = gm[wtop - k2][3];
        int s = 1 << k2;
#pragma unroll
        for (int i = 0; i < 16; i++) {
            if (i & s) continue;
            float2 p0 = v[i], p1 = v[i | s];
            float2 n0, n1;
            n0.x = m00.x * p0.x - m00.y * p0.y + m01.x * p1.x - m01.y * p1.y;
            n0.y = m00.x * p0.y + m00.y * p0.x + m01.x * p1.y + m01.y * p1.x;
            n1.x = m10.x * p0.x - m10.y * p0.y + m11.x * p1.x - m11.y * p1.y;
            n1.y = m10.x * p0.y + m10.y * p0.x + m11.x * p1.y + m11.y * p1.x;
            v[i] = n0;
            v[i | s] = n1;
        }
    }
}

// ---------------------------------------------------------------------------
// Quantum simulator: one CTA per sample, state in SMEM (swizzled).
// Per block-step: 3 fused 4-gate sweeps; CNOT-ring permutation + Z readout
// fused into sweep C's store phase.
// ---------------------------------------------------------------------------
__global__ void __launch_bounds__(256) quantum_kernel(
    const float* __restrict__ theta, const float* __restrict__ hw,
    const float* __restrict__ hb, float* __restrict__ out)
{
    __shared__ float2 st[DIM];      // 32 KB state, swizzled addressing
    __shared__ float2 gm[NQ][4];    // fused gate matrices for current step
    __shared__ float  ro[KS][NQ];   // readouts (wire-indexed)
    __shared__ float  wred[8][NQ];
    __shared__ float  xs[NQ];

    int b = blockIdx.x, t = threadIdx.x;
    if (t < NQ) xs[t] = g_x[b * NQ + t];

    // init |0...0>
#pragma unroll
    for (int g = 0; g < 16; g++) {
        int idx = t + (g << 8);
        st[physaddr(idx)] = make_float2(idx == 0 ? 1.f : 0.f, 0.f);
    }

    for (int k = 0; k < KS; k++) {
        __syncthreads();
        if (t < NQ) {
            // fused G = Rot(phi,theta,omega) * RY(x) for wire t
            float cy, sy;  sincosf(0.5f * xs[t], &sy, &cy);
            const float* th = theta + (k * NQ + t) * 3;
            float phi = th[0], tha = th[1], om = th[2];
            float ct, stt; sincosf(0.5f * tha, &stt, &ct);
            float ca, sa;  sincosf(0.5f * (phi + om), &sa, &ca); // ep = (ca,-sa)
            float cb, sb;  sincosf(0.5f * (phi - om), &sb, &cb); // em = (cb, sb)
            float r00 = ct * cy, r01 = ct * sy, r10 = stt * cy, r11 = stt * sy;
            gm[t][0] = make_float2( ca * r00 - cb * r11, -sa * r00 - sb * r11);
            gm[t][1] = make_float2(-ca * r01 - cb * r10,  sa * r01 - sb * r10);
            gm[t][2] = make_float2( cb * r10 + ca * r01, -sb * r10 + sa * r01);
            gm[t][3] = make_float2(-cb * r11 + ca * r00,  sb * r11 + sa * r00);
        }
        __syncthreads();

        float2 v[16];

        // --- sweep A: bits 8..11 (wires 3..0) ---
#pragma unroll
        for (int g = 0; g < 16; g++) v[g] = st[physaddr(t | (g << 8))];
        apply4(v, gm, 3);
#pragma unroll
        for (int g = 0; g < 16; g++) st[physaddr(t | (g << 8))] = v[g];
        __syncthreads();

        // --- sweep B: bits 4..7 (wires 7..4) ---
        int baseB = (t & 15) | ((t >> 4) << 8);
#pragma unroll
        for (int g = 0; g < 16; g++) v[g] = st[physaddr(baseB | (g << 4))];
        apply4(v, gm, 7);
#pragma unroll
        for (int g = 0; g < 16; g++) st[physaddr(baseB | (g << 4))] = v[g];
        __syncthreads();

        // --- sweep C: bits 0..3 (wires 11..8) + CNOT ring perm + readout ---
        int baseC = t << 4;
#pragma unroll
        for (int g = 0; g < 16; g++) v[g] = st[physaddr(baseC | g)];
        __syncthreads();   // all loads complete before permuted scatter
        apply4(v, gm, 11);

        float zb[NQ];
#pragma unroll
        for (int bb = 0; bb < NQ; bb++) zb[bb] = 0.f;
        float ptot = 0.f;
        int ybase = permT(baseC);
#pragma unroll
        for (int g = 0; g < 16; g++) {
            int y = permT(baseC | g);
            st[physaddr(y)] = v[g];
            float p = v[g].x * v[g].x + v[g].y * v[g].y;
            ptot += p;
            // within a group only bits {0,1,2,3,11} of y vary
            zb[0]  += ((y      ) & 1) ? -p : p;
            zb[1]  += ((y >> 1 ) & 1) ? -p : p;
            zb[2]  += ((y >> 2 ) & 1) ? -p : p;
            zb[3]  += ((y >> 3 ) & 1) ? -p : p;
            zb[11] += ((y >> 11) & 1) ? -p : p;
        }
#pragma unroll
        for (int bb = 4; bb < 11; bb++)
            zb[bb] = ((ybase >> bb) & 1) ? -ptot : ptot;

        // block reduce 12 accumulators
#pragma unroll
        for (int bb = 0; bb < NQ; bb++) {
#pragma unroll
            for (int off = 16; off; off >>= 1)
                zb[bb] += __shfl_down_sync(0xffffffffu, zb[bb], off);
        }
        int w = t >> 5, l = t & 31;
        if (l == 0) {
#pragma unroll
            for (int bb = 0; bb < NQ; bb++) wred[w][bb] = zb[bb];
        }
        __syncthreads();
        if (t < NQ) {
            float s = 0.f;
#pragma unroll
            for (int w2 = 0; w2 < 8; w2++) s += wred[w2][11 - t]; // wire t = bit 11-t
            ro[k][t] = s;
        }
    }
    __syncthreads();

    // heads + outputs.  Layout: step_logits[6,256,8] | step_readouts[6,256,12] | final[256,8]
    if (t < KS * NCLS) {
        int k = t >> 3, c = t & 7;
        float s = hb[c];
#pragma unroll
        for (int j = 0; j < NQ; j++) s += hw[c * NQ + j] * ro[k][j];
        out[(k * BATCH + b) * NCLS + c] = s;
        if (k == KS - 1)
            out[KS * BATCH * NCLS + KS * BATCH * NQ + b * NCLS + c] = s;
    }
    if (t >= 64 && t < 64 + KS * NQ) {
        int u = t - 64;
        int k = u / NQ, j = u % NQ;
        out[KS * BATCH * NCLS + (k * BATCH + b) * NQ + j] = ro[k][j];
    }
}

extern "C" void kernel_launch(void* const* d_in, const int* in_sizes, int n_in,
                              void* d_out, int out_size)
{
    const int*   ids   = (const int*)d_in[0];
    const int*   mask  = (const int*)d_in[1];
    const float* emb   = (const float*)d_in[2];
    const float* pw    = (const float*)d_in[3];
    const float* pb    = (const float*)d_in[4];
    const float* theta = (const float*)d_in[5];
    const float* hw    = (const float*)d_in[6];
    const float* hb    = (const float*)d_in[7];
    float* out = (float*)d_out;

    encoder_kernel<<<BATCH, SEQ>>>(ids, mask, emb, pw, pb);
    quantum_kernel<<<BATCH, 256>>>(theta, hw, hb, out);
}

// round 2
// speedup vs baseline: 1.0192x; 1.0192x over previous
#include <cuda_runtime.h>
#include <math.h>

#define NQ    12
#define DIM   4096
#define KS    6
#define BATCH 256
#define SEQ   128
#define DEMB  512
#define NCLS  8
#define THREADS 512

// dynamic smem layout (bytes):
//   st   [2][DIM] float2   : 65536
//   gm   [2][NQ][4] float2 :   768
//   ro   [2][KS][NQ] float :   576
//   wred [2][8][NQ] float  :   768
//   xs   [2][NQ] float     :    96
#define OFF_GM   65536
#define OFF_RO   (OFF_GM + 768)
#define OFF_WRED (OFF_RO + 576)
#define OFF_XS   (OFF_WRED + 768)
#define SMEM_BYTES (OFF_XS + 96)

__device__ __forceinline__ int physaddr(int i) { return i ^ ((i >> 4) & 0xF); }

// CNOT-ring composition: bits 0..10 = suffix parity, bit 11 = parity(bits 0..10)
__device__ __forceinline__ int permT(int x) {
    int p = x ^ (x >> 1);
    p ^= p >> 2;
    p ^= p >> 4;
    p ^= p >> 8;
    return (p & 0x7FF) | (((p ^ (x >> 11)) & 1) << 11);
}

// 4 fused single-qubit gates on a 16-amp register group; level k2 -> wire wtop-k2
__device__ __forceinline__ void apply4(float2 v[16], const float2* gm, int wtop) {
#pragma unroll
    for (int k2 = 0; k2 < 4; k2++) {
        float2 m00 = gm[(wtop - k2) * 4 + 0];
        float2 m01 = gm[(wtop - k2) * 4 + 1];
        float2 m10 = gm[(wtop - k2) * 4 + 2];
        float2 m11 = gm[(wtop - k2) * 4 + 3];
        int s = 1 << k2;
#pragma unroll
        for (int i = 0; i < 16; i++) {
            if (i & s) continue;
            float2 p0 = v[i], p1 = v[i | s];
            float2 n0, n1;
            n0.x = m00.x * p0.x - m00.y * p0.y + m01.x * p1.x - m01.y * p1.y;
            n0.y = m00.x * p0.y + m00.y * p0.x + m01.x * p1.y + m01.y * p1.x;
            n1.x = m10.x * p0.x - m10.y * p0.y + m11.x * p1.x - m11.y * p1.y;
            n1.y = m10.x * p0.y + m10.y * p0.x + m11.x * p1.y + m11.y * p1.x;
            v[i] = n0;
            v[i | s] = n1;
        }
    }
}

// ---------------------------------------------------------------------------
// Fully fused: 2 samples per 512-thread CTA, grid=128 (single wave on 148 SMs)
// ---------------------------------------------------------------------------
__global__ void __launch_bounds__(THREADS, 1) fused_kernel(
    const int* __restrict__ ids, const int* __restrict__ mask,
    const float* __restrict__ emb, const float* __restrict__ pw,
    const float* __restrict__ pb, const float* __restrict__ theta,
    const float* __restrict__ hw, const float* __restrict__ hb,
    float* __restrict__ out)
{
    extern __shared__ char sm[];
    float2* st   = (float2*)sm;                 // [2][DIM]
    float2* gm   = (float2*)(sm + OFF_GM);      // [2][NQ][4]
    float*  ro   = (float*)(sm + OFF_RO);       // [2][KS][NQ]
    float*  wred = (float*)(sm + OFF_WRED);     // [2][8][NQ]
    float*  xs   = (float*)(sm + OFF_XS);       // [2][NQ]

    int t = threadIdx.x;
    int h = t >> 8, lt = t & 255;
    int b = blockIdx.x * 2 + h;

    // ===================== encoder phase =====================
    // scratch aliased into st region (state not yet live)
    int*   sid  = (int*)sm;                   // [2][SEQ]
    float* smk  = (float*)(sm + 2 * SEQ * 4); // [2][SEQ]
    float* ered = (float*)(sm + 4 * SEQ * 4); // [2][8][13]
    if (lt < SEQ) {
        sid[h * SEQ + lt] = ids[b * SEQ + lt];
        smk[h * SEQ + lt] = (float)mask[b * SEQ + lt];
    }
    __syncthreads();

    // 256 threads/sample: dim-chunk d (4 floats), seq-half sh (64 positions)
    int d = lt & 127, sh = lt >> 7;
    float a0 = 0.f, a1 = 0.f, a2 = 0.f, a3 = 0.f, cnt = 0.f;
    for (int s = sh * 64; s < sh * 64 + 64; s++) {
        float m = smk[h * SEQ + s];
        cnt += m;
        if (m != 0.f) {
            const float4 e = __ldg((const float4*)(emb + (size_t)sid[h * SEQ + s] * DEMB + d * 4));
            a0 += m * e.x; a1 += m * e.y; a2 += m * e.z; a3 += m * e.w;
        }
    }
    // partial projection: (sum_s e)·w is linear, so reduce z-partials instead of pooled
    float z[NQ + 1];
#pragma unroll
    for (int q = 0; q < NQ; q++) {
        const float4 w = __ldg((const float4*)(pw + q * DEMB + d * 4));
        z[q] = a0 * w.x + a1 * w.y + a2 * w.z + a3 * w.w;
    }
    z[NQ] = cnt;
#pragma unroll
    for (int q = 0; q <= NQ; q++) {
#pragma unroll
        for (int off = 16; off; off >>= 1)
            z[q] += __shfl_down_sync(0xffffffffu, z[q], off);
    }
    {
        int wh = lt >> 5, l = lt & 31;
        if (l == 0) {
#pragma unroll
            for (int q = 0; q <= NQ; q++) ered[(h * 8 + wh) * 13 + q] = z[q];
        }
    }
    __syncthreads();
    if (lt < NQ) {
        float s = 0.f, c = 0.f;
#pragma unroll
        for (int w2 = 0; w2 < 8; w2++) {
            s += ered[(h * 8 + w2) * 13 + lt];
            c += ered[(h * 8 + w2) * 13 + NQ];
        }
        // c = 128 * total_mask_count (128 dim-threads share each seq-half count)
        float inv = 1.0f / fmaxf(c * (1.0f / 128.0f), 1.0f);
        xs[h * NQ + lt] = tanhf(s * inv + pb[lt]) * 3.14159265358979f;
    }
    __syncthreads();

    // ===================== quantum phase =====================
    float2* stH = st + h * DIM;
    const float2* gmH = gm + h * NQ * 4;

    // init |0...0>
#pragma unroll
    for (int g = 0; g < 16; g++) {
        int idx = lt + (g << 8);
        stH[physaddr(idx)] = make_float2(idx == 0 ? 1.f : 0.f, 0.f);
    }

    for (int k = 0; k < KS; k++) {
        __syncthreads();
        if (lt < NQ) {
            // fused G = Rot(phi,theta,omega) * RY(x) for wire lt
            float cy, sy;  sincosf(0.5f * xs[h * NQ + lt], &sy, &cy);
            const float* th = theta + (k * NQ + lt) * 3;
            float phi = th[0], tha = th[1], om = th[2];
            float ct, stt; sincosf(0.5f * tha, &stt, &ct);
            float ca, sa;  sincosf(0.5f * (phi + om), &sa, &ca); // ep = (ca,-sa)
            float cb, sb;  sincosf(0.5f * (phi - om), &sb, &cb); // em = (cb, sb)
            float r00 = ct * cy, r01 = ct * sy, r10 = stt * cy, r11 = stt * sy;
            float2* g0 = gm + (h * NQ + lt) * 4;
            g0[0] = make_float2( ca * r00 - cb * r11, -sa * r00 - sb * r11);
            g0[1] = make_float2(-ca * r01 - cb * r10,  sa * r01 - sb * r10);
            g0[2] = make_float2( cb * r10 + ca * r01, -sb * r10 + sa * r01);
            g0[3] = make_float2(-cb * r11 + ca * r00,  sb * r11 + sa * r00);
        }
        __syncthreads();

        float2 v[16];

        // --- sweep A: bits 8..11 (wires 3..0) ---
#pragma unroll
        for (int g = 0; g < 16; g++) v[g] = stH[physaddr(lt | (g << 8))];
        apply4(v, gmH, 3);
#pragma unroll
        for (int g = 0; g < 16; g++) stH[physaddr(lt | (g << 8))] = v[g];
        __syncthreads();

        // --- sweep B: bits 4..7 (wires 7..4) ---
        int baseB = (lt & 15) | ((lt >> 4) << 8);
#pragma unroll
        for (int g = 0; g < 16; g++) v[g] = stH[physaddr(baseB | (g << 4))];
        apply4(v, gmH, 7);
#pragma unroll
        for (int g = 0; g < 16; g++) stH[physaddr(baseB | (g << 4))] = v[g];
        __syncthreads();

        // --- sweep C: bits 0..3 (wires 11..8) + CNOT ring perm + readout ---
        int baseC = lt << 4;
#pragma unroll
        for (int g = 0; g < 16; g++) v[g] = stH[physaddr(baseC | g)];
        __syncthreads();   // all loads complete before permuted scatter
        apply4(v, gmH, 11);

        float zb[NQ];
#pragma unroll
        for (int bb = 0; bb < NQ; bb++) zb[bb] = 0.f;
        float ptot = 0.f;
        int ybase = permT(baseC);
#pragma unroll
        for (int g = 0; g < 16; g++) {
            int y = permT(baseC | g);
            stH[physaddr(y)] = v[g];
            float p = v[g].x * v[g].x + v[g].y * v[g].y;
            ptot += p;
            // within a group only bits {0,1,2,3,11} of y vary
            zb[0]  += ((y      ) & 1) ? -p : p;
            zb[1]  += ((y >> 1 ) & 1) ? -p : p;
            zb[2]  += ((y >> 2 ) & 1) ? -p : p;
            zb[3]  += ((y >> 3 ) & 1) ? -p : p;
            zb[11] += ((y >> 11) & 1) ? -p : p;
        }
#pragma unroll
        for (int bb = 4; bb < 11; bb++)
            zb[bb] = ((ybase >> bb) & 1) ? -ptot : ptot;

        // reduce 12 accumulators across the half's 8 warps
#pragma unroll
        for (int bb = 0; bb < NQ; bb++) {
#pragma unroll
            for (int off = 16; off; off >>= 1)
                zb[bb] += __shfl_down_sync(0xffffffffu, zb[bb], off);
        }
        int wh = lt >> 5, l = lt & 31;
        if (l == 0) {
#pragma unroll
            for (int bb = 0; bb < NQ; bb++) wred[(h * 8 + wh) * NQ + bb] = zb[bb];
        }
        __syncthreads();
        if (lt < NQ) {
            float s = 0.f;
#pragma unroll
            for (int w2 = 0; w2 < 8; w2++) s += wred[(h * 8 + w2) * NQ + (11 - lt)]; // wire lt = bit 11-lt
            ro[(h * KS + k) * NQ + lt] = s;
        }
    }
    __syncthreads();

    // heads + outputs. Layout: step_logits[6,256,8] | step_readouts[6,256,12] | final[256,8]
    if (lt < KS * NCLS) {
        int k = lt >> 3, c = lt & 7;
        float s = hb[c];
#pragma unroll
        for (int j = 0; j < NQ; j++) s += hw[c * NQ + j] * ro[(h * KS + k) * NQ + j];
        out[(k * BATCH + b) * NCLS + c] = s;
        if (k == KS - 1)
            out[KS * BATCH * NCLS + KS * BATCH * NQ + b * NCLS + c] = s;
    }
    if (lt >= 64 && lt < 64 + KS * NQ) {
        int u = lt - 64;
        int k = u / NQ, j = u % NQ;
        out[KS * BATCH * NCLS + (k * BATCH + b) * NQ + j] = ro[(h * KS + k) * NQ + j];
    }
}

extern "C" void kernel_launch(void* const* d_in, const int* in_sizes, int n_in,
                              void* d_out, int out_size)
{
    const int*   ids   = (const int*)d_in[0];
    const int*   mask  = (const int*)d_in[1];
    const float* emb   = (const float*)d_in[2];
    const float* pw    = (const float*)d_in[3];
    const float* pb    = (const float*)d_in[4];
    const float* theta = (const float*)d_in[5];
    const float* hw    = (const float*)d_in[6];
    const float* hb    = (const float*)d_in[7];
    float* out = (float*)d_out;

    cudaFuncSetAttribute(fused_kernel,
                         cudaFuncAttributeMaxDynamicSharedMemorySize, SMEM_BYTES);
    fused_kernel<<<BATCH / 2, THREADS, SMEM_BYTES>>>(ids, mask, emb, pw, pb,
                                                     theta, hw, hb, out);
}

// round 3
// speedup vs baseline: 1.0373x; 1.0178x over previous
#include <cuda_runtime.h>
#include <math.h>

#define NQ    12
#define DIM   4096
#define KS    6
#define BATCH 256
#define SEQ   128
#define DEMB  512
#define NCLS  8
#define THREADS 512

// dynamic smem layout (bytes):
//   st   [2][DIM] float2   : 65536
//   gm   [2][NQ][4] float2 :   768
//   ro   [2][KS][NQ] float :   576
//   wred [2][8][NQ] float  :   768
//   xs   [2][NQ] float     :    96
#define OFF_GM   65536
#define OFF_RO   (OFF_GM + 768)
#define OFF_WRED (OFF_RO + 576)
#define OFF_XS   (OFF_WRED + 768)
#define SMEM_BYTES (OFF_XS + 96)

__device__ __forceinline__ int physaddr(int i) { return i ^ ((i >> 4) & 0xF); }

// CNOT-ring composition: bits 0..10 = suffix parity, bit 11 = parity(bits 0..10)
__device__ __forceinline__ int permT(int x) {
    int p = x ^ (x >> 1);
    p ^= p >> 2;
    p ^= p >> 4;
    p ^= p >> 8;
    return (p & 0x7FF) | (((p ^ (x >> 11)) & 1) << 11);
}

// 4 fused single-qubit gates on a 16-amp register group; level k2 -> wire wtop-k2
__device__ __forceinline__ void apply4(float2 v[16], const float2* gm, int wtop) {
#pragma unroll
    for (int k2 = 0; k2 < 4; k2++) {
        float2 m00 = gm[(wtop - k2) * 4 + 0];
        float2 m01 = gm[(wtop - k2) * 4 + 1];
        float2 m10 = gm[(wtop - k2) * 4 + 2];
        float2 m11 = gm[(wtop - k2) * 4 + 3];
        int s = 1 << k2;
#pragma unroll
        for (int i = 0; i < 16; i++) {
            if (i & s) continue;
            float2 p0 = v[i], p1 = v[i | s];
            float2 n0, n1;
            n0.x = m00.x * p0.x - m00.y * p0.y + m01.x * p1.x - m01.y * p1.y;
            n0.y = m00.x * p0.y + m00.y * p0.x + m01.x * p1.y + m01.y * p1.x;
            n1.x = m10.x * p0.x - m10.y * p0.y + m11.x * p1.x - m11.y * p1.y;
            n1.y = m10.x * p0.y + m10.y * p0.x + m11.x * p1.y + m11.y * p1.x;
            v[i] = n0;
            v[i | s] = n1;
        }
    }
}

// ---------------------------------------------------------------------------
// Fully fused: 2 samples per 512-thread CTA, grid=128 (single wave on 148 SMs)
// ---------------------------------------------------------------------------
__global__ void __launch_bounds__(THREADS, 1) fused_kernel(
    const int* __restrict__ ids, const int* __restrict__ mask,
    const float* __restrict__ emb, const float* __restrict__ pw,
    const float* __restrict__ pb, const float* __restrict__ theta,
    const float* __restrict__ hw, const float* __restrict__ hb,
    float* __restrict__ out)
{
    extern __shared__ char sm[];
    float2* st   = (float2*)sm;                 // [2][DIM]
    float2* gm   = (float2*)(sm + OFF_GM);      // [2][NQ][4]
    float*  ro   = (float*)(sm + OFF_RO);       // [2][KS][NQ]
    float*  wred = (float*)(sm + OFF_WRED);     // [2][8][NQ]
    float*  xs   = (float*)(sm + OFF_XS);       // [2][NQ]

    int t = threadIdx.x;
    int h = t >> 8, lt = t & 255;
    int b = blockIdx.x * 2 + h;

    // ===================== encoder phase =====================
    // scratch aliased into st region (state not yet live)
    int*   sid  = (int*)sm;                   // [2][SEQ]
    float* smk  = (float*)(sm + 2 * SEQ * 4); // [2][SEQ]
    float* ered = (float*)(sm + 4 * SEQ * 4); // [2][8][13]
    if (lt < SEQ) {
        sid[h * SEQ + lt] = ids[b * SEQ + lt];
        smk[h * SEQ + lt] = (float)mask[b * SEQ + lt];
    }
    __syncthreads();

    // 256 threads/sample: dim-chunk d (4 floats), seq-half sh (64 positions)
    int d = lt & 127, sh = lt >> 7;
    float a0 = 0.f, a1 = 0.f, a2 = 0.f, a3 = 0.f, cnt = 0.f;
    for (int s = sh * 64; s < sh * 64 + 64; s++) {
        float m = smk[h * SEQ + s];
        cnt += m;
        if (m != 0.f) {
            const float4 e = __ldg((const float4*)(emb + (size_t)sid[h * SEQ + s] * DEMB + d * 4));
            a0 += m * e.x; a1 += m * e.y; a2 += m * e.z; a3 += m * e.w;
        }
    }
    // partial projection: (sum_s e)·w is linear, so reduce z-partials instead of pooled
    float z[NQ + 1];
#pragma unroll
    for (int q = 0; q < NQ; q++) {
        const float4 w = __ldg((const float4*)(pw + q * DEMB + d * 4));
        z[q] = a0 * w.x + a1 * w.y + a2 * w.z + a3 * w.w;
    }
    z[NQ] = cnt;
#pragma unroll
    for (int q = 0; q <= NQ; q++) {
#pragma unroll
        for (int off = 16; off; off >>= 1)
            z[q] += __shfl_down_sync(0xffffffffu, z[q], off);
    }
    {
        int wh = lt >> 5, l = lt & 31;
        if (l == 0) {
#pragma unroll
            for (int q = 0; q <= NQ; q++) ered[(h * 8 + wh) * 13 + q] = z[q];
        }
    }
    __syncthreads();
    if (lt < NQ) {
        float s = 0.f, c = 0.f;
#pragma unroll
        for (int w2 = 0; w2 < 8; w2++) {
            s += ered[(h * 8 + w2) * 13 + lt];
            c += ered[(h * 8 + w2) * 13 + NQ];
        }
        // c = 128 * total_mask_count (128 dim-threads share each seq-half count)
        float inv = 1.0f / fmaxf(c * (1.0f / 128.0f), 1.0f);
        xs[h * NQ + lt] = tanhf(s * inv + pb[lt]) * 3.14159265358979f;
    }
    __syncthreads();

    // ===================== quantum phase =====================
    float2* stH = st + h * DIM;
    const float2* gmH = gm + h * NQ * 4;

    // init |0...0>
#pragma unroll
    for (int g = 0; g < 16; g++) {
        int idx = lt + (g << 8);
        stH[physaddr(idx)] = make_float2(idx == 0 ? 1.f : 0.f, 0.f);
    }

    for (int k = 0; k < KS; k++) {
        __syncthreads();
        if (lt < NQ) {
            // fused G = Rot(phi,theta,omega) * RY(x) for wire lt
            float cy, sy;  sincosf(0.5f * xs[h * NQ + lt], &sy, &cy);
            const float* th = theta + (k * NQ + lt) * 3;
            float phi = th[0], tha = th[1], om = th[2];
            float ct, stt; sincosf(0.5f * tha, &stt, &ct);
            float ca, sa;  sincosf(0.5f * (phi + om), &sa, &ca); // ep = (ca,-sa)
            float cb, sb;  sincosf(0.5f * (phi - om), &sb, &cb); // em = (cb, sb)
            float r00 = ct * cy, r01 = ct * sy, r10 = stt * cy, r11 = stt * sy;
            float2* g0 = gm + (h * NQ + lt) * 4;
            g0[0] = make_float2( ca * r00 - cb * r11, -sa * r00 - sb * r11);
            g0[1] = make_float2(-ca * r01 - cb * r10,  sa * r01 - sb * r10);
            g0[2] = make_float2( cb * r10 + ca * r01, -sb * r10 + sa * r01);
            g0[3] = make_float2(-cb * r11 + ca * r00,  sb * r11 + sa * r00);
        }
        __syncthreads();

        float2 v[16];

        // --- sweep A: bits 8..11 (wires 3..0) ---
#pragma unroll
        for (int g = 0; g < 16; g++) v[g] = stH[physaddr(lt | (g << 8))];
        apply4(v, gmH, 3);
#pragma unroll
        for (int g = 0; g < 16; g++) stH[physaddr(lt | (g << 8))] = v[g];
        __syncthreads();

        // --- sweep B: bits 4..7 (wires 7..4) ---
        int baseB = (lt & 15) | ((lt >> 4) << 8);
#pragma unroll
        for (int g = 0; g < 16; g++) v[g] = stH[physaddr(baseB | (g << 4))];
        apply4(v, gmH, 7);
#pragma unroll
        for (int g = 0; g < 16; g++) stH[physaddr(baseB | (g << 4))] = v[g];
        __syncthreads();

        // --- sweep C: bits 0..3 (wires 11..8) + CNOT ring perm + readout ---
        int baseC = lt << 4;
#pragma unroll
        for (int g = 0; g < 16; g++) v[g] = stH[physaddr(baseC | g)];
        __syncthreads();   // all loads complete before permuted scatter
        apply4(v, gmH, 11);

        float zb[NQ];
#pragma unroll
        for (int bb = 0; bb < NQ; bb++) zb[bb] = 0.f;
        float ptot = 0.f;
        int ybase = permT(baseC);
#pragma unroll
        for (int g = 0; g < 16; g++) {
            int y = permT(baseC | g);
            stH[physaddr(y)] = v[g];
            float p = v[g].x * v[g].x + v[g].y * v[g].y;
            ptot += p;
            // within a group only bits {0,1,2,3,11} of y vary
            zb[0]  += ((y      ) & 1) ? -p : p;
            zb[1]  += ((y >> 1 ) & 1) ? -p : p;
            zb[2]  += ((y >> 2 ) & 1) ? -p : p;
            zb[3]  += ((y >> 3 ) & 1) ? -p : p;
            zb[11] += ((y >> 11) & 1) ? -p : p;
        }
#pragma unroll
        for (int bb = 4; bb < 11; bb++)
            zb[bb] = ((ybase >> bb) & 1) ? -ptot : ptot;

        // reduce 12 accumulators across the half's 8 warps
#pragma unroll
        for (int bb = 0; bb < NQ; bb++) {
#pragma unroll
            for (int off = 16; off; off >>= 1)
                zb[bb] += __shfl_down_sync(0xffffffffu, zb[bb], off);
        }
        int wh = lt >> 5, l = lt & 31;
        if (l == 0) {
#pragma unroll
            for (int bb = 0; bb < NQ; bb++) wred[(h * 8 + wh) * NQ + bb] = zb[bb];
        }
        __syncthreads();
        if (lt < NQ) {
            float s = 0.f;
#pragma unroll
            for (int w2 = 0; w2 < 8; w2++) s += wred[(h * 8 + w2) * NQ + (11 - lt)]; // wire lt = bit 11-lt
            ro[(h * KS + k) * NQ + lt] = s;
        }
    }
    __syncthreads();

    // heads + outputs. Layout: step_logits[6,256,8] | step_readouts[6,256,12] | final[256,8]
    if (lt < KS * NCLS) {
        int k = lt >> 3, c = lt & 7;
        float s = hb[c];
#pragma unroll
        for (int j = 0; j < NQ; j++) s += hw[c * NQ + j] * ro[(h * KS + k) * NQ + j];
        out[(k * BATCH + b) * NCLS + c] = s;
        if (k == KS - 1)
            out[KS * BATCH * NCLS + KS * BATCH * NQ + b * NCLS + c] = s;
    }
    if (lt >= 64 && lt < 64 + KS * NQ) {
        int u = lt - 64;
        int k = u / NQ, j = u % NQ;
        out[KS * BATCH * NCLS + (k * BATCH + b) * NQ + j] = ro[(h * KS + k) * NQ + j];
    }
}

extern "C" void kernel_launch(void* const* d_in, const int* in_sizes, int n_in,
                              void* d_out, int out_size)
{
    const int*   ids   = (const int*)d_in[0];
    const int*   mask  = (const int*)d_in[1];
    const float* emb   = (const float*)d_in[2];
    const float* pw    = (const float*)d_in[3];
    const float* pb    = (const float*)d_in[4];
    const float* theta = (const float*)d_in[5];
    const float* hw    = (const float*)d_in[6];
    const float* hb    = (const float*)d_in[7];
    float* out = (float*)d_out;

    cudaFuncSetAttribute(fused_kernel,
                         cudaFuncAttributeMaxDynamicSharedMemorySize, SMEM_BYTES);
    fused_kernel<<<BATCH / 2, THREADS, SMEM_BYTES>>>(ids, mask, emb, pw, pb,
                                                     theta, hw, hb, out);
}